// round 3
// baseline (speedup 1.0000x reference)
#include <cuda_runtime.h>
#include <cstdint>

#define DINL __device__ __forceinline__

// ============================ problem constants ============================
// x: [32, 64, 112, 112] f32 ; W: [64, 128, 3, 3] f32 ; out: [32, 128, 112, 112] f32
static constexpr int CI = 64, CO = 128, HW = 112;
static constexpr int TILE = 16;             // 16x16 spatial tile -> M = 256
static constexpr int RAW_W = 18;            // TILE + 2 halo
static constexpr int RAW_PITCH = 325;       // floats per ci plane (18*18 + 1 pad)

// SMEM layout (bytes)
static constexpr int SMEM_RAW   = 0;        // 64 * 325 * 4 = 83200
static constexpr int B_PITCH_F  = 132;      // floats per k-row of B tile (128 data + 4 pad)
static constexpr int B_BUF_B    = 64 * B_PITCH_F * 4;   // 33792 bytes per buffer
static constexpr int SMEM_B     = 83200;    // 2 buffers -> 67584
static constexpr int SMEM_TOTAL = 83200 + 2 * B_BUF_B;  // 150784
// epilogue staging (reuses [0, 133120) after mainloop): sOut[m=256][co], pitch 130 floats
static constexpr int SOUT_PITCH_F = 130;

// Pre-transposed, tf32-rounded weights: Wt[tap][ci][co], 9*64*128 floats.
static __device__ float g_Wt[9 * 64 * 128];

// ============================ weight transpose ============================

__global__ void wt_transpose_kernel(const float* __restrict__ W) {
    int i = blockIdx.x * 256 + threadIdx.x;
    if (i >= 9 * 64 * 128) return;
    int co  = i & 127;
    int ci  = (i >> 7) & 63;
    int tap = i >> 13;
    float w = W[(ci * 128 + co) * 9 + tap];
    uint32_t t;
    asm("cvt.rna.tf32.f32 %0, %1;" : "=r"(t) : "f"(w));
    g_Wt[i] = __uint_as_float(t);
}

// ============================ helpers ============================

DINL uint32_t smem_u32(const void* p) {
    uint32_t a;
    asm("{ .reg .u64 t; cvta.to.shared.u64 t, %1; cvt.u32.u64 %0, t; }"
        : "=r"(a) : "l"(p));
    return a;
}

DINL void cp_async16(uint32_t smem_addr, const void* gptr) {
    asm volatile("cp.async.ca.shared.global [%0], [%1], 16;"
                 :: "r"(smem_addr), "l"(gptr) : "memory");
}
DINL void cp_commit() { asm volatile("cp.async.commit_group;" ::: "memory"); }
DINL void cp_wait1()  { asm volatile("cp.async.wait_group 1;" ::: "memory"); }
DINL void cp_wait0()  { asm volatile("cp.async.wait_group 0;" ::: "memory"); }

DINL uint32_t f2tf32(float f) {
    uint32_t t;
    asm("cvt.rna.tf32.f32 %0, %1;" : "=r"(t) : "f"(f));
    return t;
}

DINL void mma_tf32(float& c0, float& c1, float& c2, float& c3,
                   uint32_t a0, uint32_t a1, uint32_t a2, uint32_t a3,
                   uint32_t b0, uint32_t b1) {
    asm volatile(
        "mma.sync.aligned.m16n8k8.row.col.f32.tf32.tf32.f32 "
        "{%0,%1,%2,%3}, {%4,%5,%6,%7}, {%8,%9}, {%0,%1,%2,%3};"
        : "+f"(c0), "+f"(c1), "+f"(c2), "+f"(c3)
        : "r"(a0), "r"(a1), "r"(a2), "r"(a3), "r"(b0), "r"(b1));
}

// ============================ main conv kernel ============================

__global__ void __launch_bounds__(256, 1)
conv_mma_kernel(const float* __restrict__ x, float* __restrict__ out) {
    extern __shared__ char smem[];
    const uint32_t sb = smem_u32(smem);
    const int tid = threadIdx.x, wid = tid >> 5, lid = tid & 31;
    const int g = lid >> 2, tig = lid & 3;        // mma quad decomposition
    const int wm = wid & 3, wn = wid >> 2;        // 4 m-warps x 2 n-warps

    const int blk = blockIdx.x;                   // 32*7*7 = 1568 CTAs
    const int n   = blk / 49;
    const int rem = blk % 49;
    const int h0  = (rem / 7) * TILE;
    const int w0  = (rem % 7) * TILE;

    float* raw = (float*)(smem + SMEM_RAW);

    // ---- prefetch weight tap 0 into B buffer 0 (cp.async) ----
    {
        const float* wsrc = g_Wt;                 // tap 0
        #pragma unroll
        for (int it = 0; it < 8; it++) {
            int j = it * 256 + tid;               // 2048 16B-chunks
            int row = j >> 5, col = j & 31;
            cp_async16(sb + SMEM_B + row * (B_PITCH_F * 4) + col * 16,
                       wsrc + row * 128 + col * 4);
        }
        cp_commit();
    }

    // ---- load raw input tile (64ci x 18x18) with zero halo ----
    const float* xn = x + (size_t)n * CI * (HW * HW);
    for (int i = tid; i < CI * 324; i += 256) {
        int ci = i / 324, r = i % 324, hh = r / RAW_W, ww = r % RAW_W;
        int gh = h0 - 1 + hh, gw = w0 - 1 + ww;
        float v = 0.0f;
        if ((unsigned)gh < (unsigned)HW && (unsigned)gw < (unsigned)HW)
            v = __ldg(xn + ci * (HW * HW) + gh * HW + gw);
        raw[ci * RAW_PITCH + hh * RAW_W + ww] = v;
    }

    float acc[4][8][4];
    #pragma unroll
    for (int mt = 0; mt < 4; mt++)
        #pragma unroll
        for (int nt = 0; nt < 8; nt++)
            #pragma unroll
            for (int q = 0; q < 4; q++) acc[mt][nt][q] = 0.0f;

    for (int tap = 0; tap < 9; tap++) {
        // prefetch next tap's weights into the other buffer
        if (tap < 8) {
            const float* wsrc = g_Wt + (tap + 1) * 8192;
            uint32_t bdst = sb + SMEM_B + ((tap + 1) & 1) * B_BUF_B;
            #pragma unroll
            for (int it = 0; it < 8; it++) {
                int j = it * 256 + tid;
                int row = j >> 5, col = j & 31;
                cp_async16(bdst + row * (B_PITCH_F * 4) + col * 16,
                           wsrc + row * 128 + col * 4);
            }
            cp_commit();
            cp_wait1();            // current tap's group complete
        } else {
            cp_wait0();
        }
        __syncthreads();           // raw (tap 0) + current B visible CTA-wide

        const float* Bb = (const float*)(smem + SMEM_B + (tap & 1) * B_BUF_B);
        const int u = tap / 3, v = tap - u * 3;

        int aoff[4];
        #pragma unroll
        for (int mt = 0; mt < 4; mt++)
            aoff[mt] = (wm * 4 + mt + u) * RAW_W + g + v;

        #pragma unroll 2
        for (int kc = 0; kc < 8; kc++) {
            const int cb = (kc * 8 + tig) * RAW_PITCH;

            uint32_t a[4][4];
            #pragma unroll
            for (int mt = 0; mt < 4; mt++) {
                a[mt][0] = f2tf32(raw[cb + aoff[mt]]);                  // [g][tig]
                a[mt][1] = f2tf32(raw[cb + aoff[mt] + 8]);              // [g+8][tig]
                a[mt][2] = f2tf32(raw[cb + 4 * RAW_PITCH + aoff[mt]]);  // [g][tig+4]
                a[mt][3] = f2tf32(raw[cb + 4 * RAW_PITCH + aoff[mt] + 8]);
            }

            const int bb = (kc * 8 + tig) * B_PITCH_F + wn * 64 + g;
            uint32_t b[8][2];
            #pragma unroll
            for (int nt = 0; nt < 8; nt++) {
                b[nt][0] = __float_as_uint(Bb[bb + nt * 8]);                 // [tig][n]
                b[nt][1] = __float_as_uint(Bb[bb + 4 * B_PITCH_F + nt * 8]); // [tig+4][n]
            }

            #pragma unroll
            for (int mt = 0; mt < 4; mt++)
                #pragma unroll
                for (int nt = 0; nt < 8; nt++)
                    mma_tf32(acc[mt][nt][0], acc[mt][nt][1],
                             acc[mt][nt][2], acc[mt][nt][3],
                             a[mt][0], a[mt][1], a[mt][2], a[mt][3],
                             b[nt][0], b[nt][1]);
        }
        __syncthreads();           // done reading this B buffer before it's rewritten
    }

    // ---- epilogue: regs -> SMEM transpose -> coalesced NCHW stores ----
    float* sOut = (float*)smem;    // reuses raw/B region: 256 * 130 * 4 = 133120 B
    #pragma unroll
    for (int mt = 0; mt < 4; mt++) {
        const int m0 = wm * 64 + mt * 16 + g;
        #pragma unroll
        for (int nt = 0; nt < 8; nt++) {
            const int co = wn * 64 + nt * 8 + 2 * tig;
            *(float2*)(sOut + m0 * SOUT_PITCH_F + co) =
                make_float2(acc[mt][nt][0], acc[mt][nt][1]);
            *(float2*)(sOut + (m0 + 8) * SOUT_PITCH_F + co) =
                make_float2(acc[mt][nt][2], acc[mt][nt][3]);
        }
    }
    __syncthreads();

    float* ob = out + (size_t)n * CO * (HW * HW);
    #pragma unroll 4
    for (int it = 0; it < 128; it++) {
        int idx = it * 256 + tid;          // idx = co*256 + m
        int m  = idx & 255;
        int co = idx >> 8;
        int mh = m >> 4, mw = m & 15;
        ob[(size_t)co * (HW * HW) + (h0 + mh) * HW + (w0 + mw)] =
            sOut[m * SOUT_PITCH_F + co];
    }
}

// ============================ launch ============================

extern "C" void kernel_launch(void* const* d_in, const int* in_sizes, int n_in,
                              void* d_out, int out_size) {
    const float* x = (const float*)d_in[0];
    const float* W = (const float*)d_in[1];
    // Input-order insurance: x has 25,690,112 elements, W has 73,728.
    if (n_in >= 2 && in_sizes[0] < in_sizes[1]) {
        const float* t = x; x = W; W = t;
    }
    float* out = (float*)d_out;

    wt_transpose_kernel<<<288, 256>>>(W);

    cudaFuncSetAttribute(conv_mma_kernel,
                         cudaFuncAttributeMaxDynamicSharedMemorySize, SMEM_TOTAL);
    conv_mma_kernel<<<1568, 256, SMEM_TOTAL>>>(x, out);
}

// round 4
// speedup vs baseline: 1.4946x; 1.4946x over previous
#include <cuda_runtime.h>
#include <cuda_fp16.h>
#include <cstdint>

#define DINL __device__ __forceinline__

// ============================ problem constants ============================
// x: [32, 64, 112, 112] f32 ; W: [64, 128, 3, 3] f32 ; out: [32, 128, 112, 112] f32
static constexpr int CI = 64, CO = 128, HW = 112;
static constexpr int TILE = 16;             // 16x16 spatial tile -> M = 256
static constexpr int RAW_W = 18;            // TILE + 2 halo

// raw2: 32 planes of half2 (ci pairs interleaved), [p][hh*18+ww]
// plane pitch in 4-byte words: 324 data + 4 pad = 328  (328 % 32 == 8 -> A loads conflict-free)
static constexpr int P2 = 328;
static constexpr int RAW2_BYTES = 32 * P2 * 4;          // 41984

// B tile: half [co][ci], word pitch per co = 36 (64 halves + 8 pad; 36 % 32 == 4 -> conflict-free)
static constexpr int BPW = 36;
static constexpr int B_BUF_B = 128 * BPW * 4;           // 18432 bytes
static constexpr int SMEM_B = RAW2_BYTES;               // 3 buffers follow raw2

// epilogue staging (reuses whole smem): sOut[m=256][co], pitch 130 floats = 133120 B
static constexpr int SOUT_PITCH_F = 130;
static constexpr int SMEM_TOTAL = 256 * SOUT_PITCH_F * 4;   // 133120 > 41984+3*18432=97280

// Pre-transposed fp16 weights: Wh[tap][co][ci], 9*128*64 halves.
static __device__ unsigned short g_Wh[9 * 128 * 64];

// ============================ weight transpose ============================

__global__ void wt_transpose_kernel(const float* __restrict__ W) {
    int i = blockIdx.x * 256 + threadIdx.x;     // i = tap*8192 + co*64 + ci
    if (i >= 9 * 128 * 64) return;
    int ci  = i & 63;
    int co  = (i >> 6) & 127;
    int tap = i >> 13;
    __half h = __float2half_rn(W[(ci * 128 + co) * 9 + tap]);
    g_Wh[i] = __half_as_ushort(h);
}

// ============================ helpers ============================

DINL uint32_t smem_u32(const void* p) {
    uint32_t a;
    asm("{ .reg .u64 t; cvta.to.shared.u64 t, %1; cvt.u32.u64 %0, t; }"
        : "=r"(a) : "l"(p));
    return a;
}

DINL void cp_async16(uint32_t smem_addr, const void* gptr) {
    asm volatile("cp.async.ca.shared.global [%0], [%1], 16;"
                 :: "r"(smem_addr), "l"(gptr) : "memory");
}
DINL void cp_commit() { asm volatile("cp.async.commit_group;" ::: "memory"); }
DINL void cp_wait1()  { asm volatile("cp.async.wait_group 1;" ::: "memory"); }
DINL void cp_wait0()  { asm volatile("cp.async.wait_group 0;" ::: "memory"); }

DINL void mma_f16(float& c0, float& c1, float& c2, float& c3,
                  uint32_t a0, uint32_t a1, uint32_t a2, uint32_t a3,
                  uint32_t b0, uint32_t b1) {
    asm volatile(
        "mma.sync.aligned.m16n8k16.row.col.f32.f16.f16.f32 "
        "{%0,%1,%2,%3}, {%4,%5,%6,%7}, {%8,%9}, {%0,%1,%2,%3};"
        : "+f"(c0), "+f"(c1), "+f"(c2), "+f"(c3)
        : "r"(a0), "r"(a1), "r"(a2), "r"(a3), "r"(b0), "r"(b1));
}

// ============================ main conv kernel ============================

__global__ void __launch_bounds__(256, 1)
conv_mma_kernel(const float* __restrict__ x, float* __restrict__ out) {
    extern __shared__ char smem[];
    const uint32_t sb = smem_u32(smem);
    const int tid = threadIdx.x, wid = tid >> 5, lid = tid & 31;
    const int g = lid >> 2, tig = lid & 3;        // mma quad decomposition
    const int wm = wid & 3, wn = wid >> 2;        // 4 m-warps x 2 n-warps

    const int blk = blockIdx.x;                   // 32*7*7 = 1568 CTAs
    const int n   = blk / 49;
    const int rem = blk % 49;
    const int h0  = (rem / 7) * TILE;
    const int w0  = (rem % 7) * TILE;

    // ---- prefetch weight tap 0 into B buffer 0 (cp.async) ----
    {
        const unsigned short* wsrc = g_Wh;        // tap 0
        #pragma unroll
        for (int it = 0; it < 4; it++) {
            int j = it * 256 + tid;               // 1024 16B-chunks
            int row = j >> 3, col = j & 7;        // row = co, col = 8-half chunk
            cp_async16(sb + SMEM_B + row * (BPW * 4) + col * 16,
                       wsrc + row * 64 + col * 8);
        }
        cp_commit();
    }

    // ---- load input tile: fp32 gmem -> fp16, ci-pair interleaved half2 planes ----
    // raw2[p][hh*18+ww] = half2(x[2p], x[2p+1]) at spatial (hh,ww)
    unsigned short* rawh = (unsigned short*)smem;  // element view (2B)
    const float* xn = x + (size_t)n * CI * (HW * HW);
    for (int i = tid; i < CI * 324; i += 256) {
        int ci = i / 324, r = i % 324, hh = r / RAW_W, ww = r % RAW_W;
        int gh = h0 - 1 + hh, gw = w0 - 1 + ww;
        float v = 0.0f;
        if ((unsigned)gh < (unsigned)HW && (unsigned)gw < (unsigned)HW)
            v = __ldg(xn + ci * (HW * HW) + gh * HW + gw);
        // word index (ci>>1)*P2 + r, half slot (ci&1)
        rawh[((ci >> 1) * P2 + r) * 2 + (ci & 1)] = __half_as_ushort(__float2half_rn(v));
    }

    float acc[4][8][4];
    #pragma unroll
    for (int mt = 0; mt < 4; mt++)
        #pragma unroll
        for (int nt = 0; nt < 8; nt++)
            #pragma unroll
            for (int q = 0; q < 4; q++) acc[mt][nt][q] = 0.0f;

    const uint32_t* raw2w = (const uint32_t*)smem;

    for (int tap = 0; tap < 9; tap++) {
        // prefetch next tap's weights into buffer (tap+1)%3
        if (tap < 8) {
            const unsigned short* wsrc = g_Wh + (tap + 1) * 8192;
            uint32_t bdst = sb + SMEM_B + ((tap + 1) % 3) * B_BUF_B;
            #pragma unroll
            for (int it = 0; it < 4; it++) {
                int j = it * 256 + tid;
                int row = j >> 3, col = j & 7;
                cp_async16(bdst + row * (BPW * 4) + col * 16,
                           wsrc + row * 64 + col * 8);
            }
            cp_commit();
            cp_wait1();            // current tap's group complete
        } else {
            cp_wait0();
        }
        __syncthreads();           // raw2 (tap 0) + current B visible CTA-wide

        const uint32_t* Bw = (const uint32_t*)(smem + SMEM_B + (tap % 3) * B_BUF_B);
        const int u = tap / 3, v = tap - u * 3;

        int aoff[4];
        #pragma unroll
        for (int mt = 0; mt < 4; mt++)
            aoff[mt] = (wm * 4 + mt + u) * RAW_W + g + v;

        const int bb = (wn * 64 + g) * BPW + tig;

        #pragma unroll 2
        for (int kc = 0; kc < 4; kc++) {           // k16 chunks over ci=64
            const uint32_t* pl0 = raw2w + (kc * 8 + tig) * P2;       // k = kc*16 + 2tig
            const uint32_t* pl2 = pl0 + 4 * P2;                      // k + 8

            uint32_t a[4][4];
            #pragma unroll
            for (int mt = 0; mt < 4; mt++) {
                a[mt][0] = pl0[aoff[mt]];          // rows (g), cols (2tig,2tig+1)
                a[mt][1] = pl0[aoff[mt] + 8];      // rows (g+8)
                a[mt][2] = pl2[aoff[mt]];          // cols (2tig+8,2tig+9)
                a[mt][3] = pl2[aoff[mt] + 8];
            }

            uint32_t b[8][2];
            #pragma unroll
            for (int nt = 0; nt < 8; nt++) {
                b[nt][0] = Bw[bb + nt * 8 * BPW + kc * 8];       // k = kc*16+2tig,+1
                b[nt][1] = Bw[bb + nt * 8 * BPW + kc * 8 + 4];   // k + 8
            }

            #pragma unroll
            for (int mt = 0; mt < 4; mt++)
                #pragma unroll
                for (int nt = 0; nt < 8; nt++)
                    mma_f16(acc[mt][nt][0], acc[mt][nt][1],
                            acc[mt][nt][2], acc[mt][nt][3],
                            a[mt][0], a[mt][1], a[mt][2], a[mt][3],
                            b[nt][0], b[nt][1]);
        }
        // no trailing barrier: 3 B buffers + the single sync per tap make rewrites safe
    }

    __syncthreads();               // everyone done reading raw2/B before sOut overwrite

    // ---- epilogue: regs -> SMEM transpose -> coalesced NCHW stores ----
    float* sOut = (float*)smem;    // 256 * 130 * 4 = 133120 B
    #pragma unroll
    for (int mt = 0; mt < 4; mt++) {
        const int m0 = wm * 64 + mt * 16 + g;
        #pragma unroll
        for (int nt = 0; nt < 8; nt++) {
            const int co = wn * 64 + nt * 8 + 2 * tig;
            *(float2*)(sOut + m0 * SOUT_PITCH_F + co) =
                make_float2(acc[mt][nt][0], acc[mt][nt][1]);
            *(float2*)(sOut + (m0 + 8) * SOUT_PITCH_F + co) =
                make_float2(acc[mt][nt][2], acc[mt][nt][3]);
        }
    }
    __syncthreads();

    float* ob = out + (size_t)n * CO * (HW * HW);
    #pragma unroll 4
    for (int it = 0; it < 128; it++) {
        int idx = it * 256 + tid;          // idx = co*256 + m
        int m  = idx & 255;
        int co = idx >> 8;
        int mh = m >> 4, mw = m & 15;
        ob[(size_t)co * (HW * HW) + (h0 + mh) * HW + (w0 + mw)] =
            sOut[m * SOUT_PITCH_F + co];
    }
}

// ============================ launch ============================

extern "C" void kernel_launch(void* const* d_in, const int* in_sizes, int n_in,
                              void* d_out, int out_size) {
    const float* x = (const float*)d_in[0];
    const float* W = (const float*)d_in[1];
    // Input-order insurance: x has 25,690,112 elements, W has 73,728.
    if (n_in >= 2 && in_sizes[0] < in_sizes[1]) {
        const float* t = x; x = W; W = t;
    }
    float* out = (float*)d_out;

    wt_transpose_kernel<<<288, 256>>>(W);

    cudaFuncSetAttribute(conv_mma_kernel,
                         cudaFuncAttributeMaxDynamicSharedMemorySize, SMEM_TOTAL);
    conv_mma_kernel<<<1568, 256, SMEM_TOTAL>>>(x, out);
}